// round 16
// baseline (speedup 1.0000x reference)
#include <cuda_runtime.h>
#include <math.h>

#define NN 50000
#define NE 400000
#define NG 64
#define DIN 200
#define DH 32
#define NBLK 196    // ceil(NN/256)
#define EBLK2 782   // ceil(NE/512)  (hist: 256 thr x 2 edges)
#define GBLK 391    // ceil(NN/128)  (GEMM blocks: 256 thr, 128 nodes, 64 cols)
#define SCB 782     // ceil(NE/512)  (scatter blocks: 256 thr x 2 edges)

typedef unsigned long long ull;

// ---------------- scratch (device globals — no allocation allowed) ----------
// NOTE: never pass these as kernel args from host code (host shadow symbol +
// ATS silently reads zeros). Select ping-pong buffers with an int in device
// code. ALL scratch explicitly zeroed at the top of every launch — replays
// identical by construction. NO __threadfence (per-block CCTL.IVALL = L1D
// flush; measured disaster). Pre-duplicate the BROADCAST operand only (X / h),
// never the per-lane streamed operand (W) — round 13's W-dup doubled strided
// LDS traffic and regressed 2.3x. Keep smem bytes/FMA2 <= ~10 (crossbar).
__device__ __align__(16) float g_tr_a[NN * DH];
__device__ __align__(16) float g_tr_b[NN * DH];
__device__ __align__(16) float g_root_a[NN * DH];
__device__ __align__(16) float g_root_b[NN * DH];
__device__ float g_sums[NG * DH];

__device__ int g_flag_ei;    // nonzero -> edge_index is int32
__device__ int g_flag_b;     // nonzero -> batch is int32

__device__ int g_cnt[NN];
__device__ int g_off[NN];
__device__ int g_cur[NN];
__device__ int g_total;
__device__ int g_esrc[NE];
__device__ int g_gstart[NG + 1];

__device__ __forceinline__ float elu1(float v) { return v > 0.f ? v : expm1f(v); }

#define FMA_X2(acc, a, b) \
    asm("fma.rn.f32x2 %0, %1, %2, %0;" : "+l"(acc) : "l"(a), "l"(b))
#define DUP_X2(out, x) \
    asm("mov.b64 %0, {%1, %1};" : "=l"(out) : "r"(__float_as_uint(x)))
#define UNPK_X2(lo, hi, in) \
    asm("mov.b64 {%0, %1}, %2;" : "=f"(lo), "=f"(hi) : "l"(in))
#define PACK_X2(out, lo, hi) \
    asm("mov.b64 %0, {%1, %2};" : "=l"(out) : "f"(lo), "f"(hi))

// ---------------------------------------------------------------------------
// dtype decode helpers (clamped)
// ---------------------------------------------------------------------------
__device__ __forceinline__ int edge_at(const void* ei_raw, int idx, int is32)
{
    int v = is32 ? ((const int*)ei_raw)[idx] : (int)((const long long*)ei_raw)[idx];
    v &= 0x7fffffff;
    return (v < NN) ? v : 0;
}

__device__ __forceinline__ int batch_at(const void* b_raw, int i, int is32)
{
    int g = is32 ? ((const int*)b_raw)[i] : (int)((const long long*)b_raw)[i];
    g &= 0x7fffffff;
    return (g < NG) ? g : (NG - 1);
}

// ---------------------------------------------------------------------------
// Kernel 1: zero scratch + dtype detection (block 0 samples odd 32-bit words:
// int64 values < 2^31 have zero high words; int32 payloads essentially never do)
// ---------------------------------------------------------------------------
__global__ void k_detect_zero(const unsigned* __restrict__ ei_w,
                              const unsigned* __restrict__ b_w)
{
    const int i = blockIdx.x * blockDim.x + threadIdx.x;
    if (i < NN) g_cnt[i] = 0;
    if (i < NG * DH) g_sums[i] = 0.f;
    if (i == 0) g_total = 0;

    if (blockIdx.x == 0) {
        __shared__ int s_ei, s_b;
        const int tid = threadIdx.x;
        if (tid == 0) { s_ei = 0; s_b = 0; }
        __syncthreads();
        { const int k = tid * 1562;  if (ei_w[2 * k + 1] != 0) atomicOr(&s_ei, 1); }
        { const int k = 24744 + tid; if (b_w[2 * k + 1] != 0)  atomicOr(&s_b, 1); }
        __syncthreads();
        if (tid == 0) { g_flag_ei = s_ei; g_flag_b = s_b; }
    }
}

// ---------------------------------------------------------------------------
// Kernel 2: dst histogram (decodes only dst half of raw edge_index)
// ---------------------------------------------------------------------------
__global__ void k_hist(const void* __restrict__ ei_raw)
{
    const int tid = blockIdx.x * 256 + threadIdx.x;
    const int is32 = g_flag_ei;
#pragma unroll
    for (int q = 0; q < 2; q++) {
        const int e = tid + q * (EBLK2 * 256);
        if (e < NE) atomicAdd(&g_cnt[edge_at(ei_raw, NE + e, is32)], 1);
    }
}

// ---------------------------------------------------------------------------
// Kernel 3: single-pass scan (block scan + atomic base; bases need not be
// monotone since consumers use beg + cnt) fused with graph-boundary build.
// ---------------------------------------------------------------------------
__global__ void k_scan_bounds(const void* __restrict__ b_raw)
{
    __shared__ int s[256];
    __shared__ int base_sh;
    const int tid = threadIdx.x;
    const int i = blockIdx.x * 256 + tid;
    const int v = (i < NN) ? g_cnt[i] : 0;
    s[tid] = v;
    __syncthreads();
#pragma unroll
    for (int d = 1; d < 256; d <<= 1) {
        const int t = (tid >= d) ? s[tid - d] : 0;
        __syncthreads();
        s[tid] += t;
        __syncthreads();
    }
    if (tid == 255) base_sh = atomicAdd(&g_total, s[255]);
    __syncthreads();
    if (i < NN) {
        const int o = base_sh + s[tid] - v;
        g_off[i] = o;
        g_cur[i] = o;
    }

    if (i < NN) {
        const int is32 = g_flag_b;
        const int g  = batch_at(b_raw, i, is32);
        const int gp = (i == 0) ? -1 : batch_at(b_raw, i - 1, is32);
        for (int q = gp + 1; q <= g; q++) g_gstart[q] = i;
        if (i == NN - 1)
            for (int q = g + 1; q <= NG; q++) g_gstart[q] = NN;
    }
}

// ---------------------------------------------------------------------------
// Kernel 4 (fused): blocks [0,GBLK) = GEMM1; blocks [GBLK,GBLK+SCB) = CSR
// scatter (decodes raw edges directly).
// GEMM1: [50000,200] @ [W1r|W1l][200,64], packed f32x2, double-buffered smem.
// 256 threads / 128 nodes / 64 cols; 8 nodes x 4 cols per thread.
// X staged PRE-DUPLICATED as (x,x) ull pairs -> inner loop has ZERO DUPs:
// per kk = 4 LDS.128(X bcast) + 1 LDS.128(W) + 16 FMA2.
// ---------------------------------------------------------------------------
__global__ __launch_bounds__(256) void k_gemm1_scatter(const float* __restrict__ x,
                                                       const float* __restrict__ Wr,
                                                       const float* __restrict__ Wl,
                                                       const float* __restrict__ b,
                                                       const void* __restrict__ ei_raw)
{
    if (blockIdx.x >= GBLK) {
        const int base = (blockIdx.x - GBLK) * 512 + threadIdx.x;
        const int is32 = g_flag_ei;
#pragma unroll
        for (int q = 0; q < 2; q++) {
            const int e = base + q * 256;
            if (e < NE) {
                const int d = edge_at(ei_raw, NE + e, is32);
                const int s = edge_at(ei_raw, e, is32);
                const int pos = atomicAdd(&g_cur[d], 1);
                g_esrc[pos] = s;
            }
        }
        return;
    }

    __shared__ __align__(16) ull   Xs2[2][8 * 128];  // [buf][k][node] = (x,x)
    __shared__ __align__(16) float Wsc[2][8 * 64];   // [buf][k*64+c]
    __shared__ float bs[32];

    const int tid = threadIdx.x;
    const int n0  = blockIdx.x * 128;
    if (tid < 32) bs[tid] = b[tid];

    const int cg = tid & 15;       // col group (4 cols), 0..15
    const int ng = tid >> 4;       // node group (8 nodes), 0..15

    ull acc2[8][2];                // [node][col pair]
#pragma unroll
    for (int i = 0; i < 8; i++) { acc2[i][0] = 0ULL; acc2[i][1] = 0ULL; }

    const bool is_x = tid < 128;
    const int  nld = n0 + tid;
    const bool vld = is_x && (nld < NN);
    const float4* xrow = reinterpret_cast<const float4*>(x + (long)nld * DIN);

    float4 xa, xb;
    float  wv[2];

#define LOAD_TILE(t)                                                          \
    do {                                                                      \
        if (is_x) {                                                           \
            xa = make_float4(0.f, 0.f, 0.f, 0.f); xb = xa;                    \
            if (vld) { xa = xrow[(t) * 2]; xb = xrow[(t) * 2 + 1]; }          \
        }                                                                     \
        _Pragma("unroll")                                                     \
        for (int j = 0; j < 2; j++) {                                         \
            const int idx = j * 256 + tid;       /* 0..511 = kk*64+c */       \
            const int kk = idx >> 6, c = idx & 63;                            \
            wv[j] = (c < 32) ? Wr[((t) * 8 + kk) * 32 + c]                    \
                             : Wl[((t) * 8 + kk) * 32 + c - 32];              \
        }                                                                     \
    } while (0)

#define STORE_TILE(bf)                                                        \
    do {                                                                      \
        if (is_x) {                                                           \
            ull d0, d1, d2, d3, d4, d5, d6, d7;                               \
            DUP_X2(d0, xa.x); DUP_X2(d1, xa.y);                               \
            DUP_X2(d2, xa.z); DUP_X2(d3, xa.w);                               \
            DUP_X2(d4, xb.x); DUP_X2(d5, xb.y);                               \
            DUP_X2(d6, xb.z); DUP_X2(d7, xb.w);                               \
            Xs2[bf][0 * 128 + tid] = d0; Xs2[bf][1 * 128 + tid] = d1;         \
            Xs2[bf][2 * 128 + tid] = d2; Xs2[bf][3 * 128 + tid] = d3;         \
            Xs2[bf][4 * 128 + tid] = d4; Xs2[bf][5 * 128 + tid] = d5;         \
            Xs2[bf][6 * 128 + tid] = d6; Xs2[bf][7 * 128 + tid] = d7;         \
        }                                                                     \
        _Pragma("unroll")                                                     \
        for (int j = 0; j < 2; j++) Wsc[bf][j * 256 + tid] = wv[j];           \
    } while (0)

    LOAD_TILE(0);
    STORE_TILE(0);
    __syncthreads();

    int buf = 0;
    for (int t = 0; t < 25; t++) {
        if (t < 24) LOAD_TILE(t + 1);                // LDG in flight during compute

#pragma unroll
        for (int kk = 0; kk < 8; kk++) {
            const ulonglong2* xp =
                reinterpret_cast<const ulonglong2*>(Xs2[buf] + kk * 128 + ng * 8);
            const ulonglong2 p0 = xp[0], p1 = xp[1], p2 = xp[2], p3 = xp[3];
            const ull* wp =
                reinterpret_cast<const ull*>(Wsc[buf] + kk * 64 + cg * 4);
            const ull w0 = wp[0], w1p = wp[1];
            const ull xd[8] = {p0.x, p0.y, p1.x, p1.y, p2.x, p2.y, p3.x, p3.y};
#pragma unroll
            for (int i = 0; i < 8; i++) {
                FMA_X2(acc2[i][0], xd[i], w0);
                FMA_X2(acc2[i][1], xd[i], w1p);
            }
        }

        if (t < 24) STORE_TILE(buf ^ 1);             // other buffer: race-free
        __syncthreads();
        buf ^= 1;
    }
#undef LOAD_TILE
#undef STORE_TILE

    const int c0 = cg * 4;
#pragma unroll
    for (int i = 0; i < 8; i++) {
        const int node = n0 + ng * 8 + i;
        if (node >= NN) continue;
        float c[4];
        UNPK_X2(c[0], c[1], acc2[i][0]);
        UNPK_X2(c[2], c[3], acc2[i][1]);
        float4 v = make_float4(c[0], c[1], c[2], c[3]);
        if (cg < 8) {
            *reinterpret_cast<float4*>(g_tr_a + node * DH + c0) = v;
        } else {
            const int cc = c0 - 32;
            v.x += bs[cc + 0]; v.y += bs[cc + 1]; v.z += bs[cc + 2]; v.w += bs[cc + 3];
            *reinterpret_cast<float4*>(g_root_a + node * DH + cc) = v;
        }
    }
}

// ---------------------------------------------------------------------------
// Fused layer kernel (layers 1->2, 2->3): warp per node; buffers picked by sel
// in device code. Gather MLP=8. h stored PRE-DUPLICATED as (h,h) -> GEMM tail
// has zero DUPs (LDS.64 broadcast + FMA2 only).
// ---------------------------------------------------------------------------
__global__ __launch_bounds__(256) void k_flayer(int sel,
                                                const float* __restrict__ Wr,
                                                const float* __restrict__ Wl,
                                                const float* __restrict__ b)
{
    __shared__ __align__(16) ull Wp[32 * 32];  // [k][lane]=(Wr,Wl)
    __shared__ __align__(16) ull hs2[8][32];   // [warp][k] = (h,h)
    __shared__ float bs[32];

    const int tid = threadIdx.x;
    for (int i = tid; i < 1024; i += 256) {
        const int k = i >> 5, c = i & 31;
        ull p;
        PACK_X2(p, Wr[k * 32 + c], Wl[k * 32 + c]);
        Wp[i] = p;
    }
    if (tid < 32) bs[tid] = b[tid];
    __syncthreads();

    const float* tr_in   = sel ? g_tr_b   : g_tr_a;
    const float* root_in = sel ? g_root_b : g_root_a;
    float* tr_out   = sel ? g_tr_a   : g_tr_b;
    float* root_out = sel ? g_root_a : g_root_b;

    const int w    = tid >> 5;
    const int lane = tid & 31;
    const int node = (blockIdx.x << 3) + w;
    if (node >= NN) return;

    const int beg = g_off[node];
    const int end = beg + g_cnt[node];
    float acc = 0.f;
    int k = beg;
    for (; k + 7 < end; k += 8) {                 // MLP=8 over L2-latency gathers
        const int s0 = g_esrc[k + 0], s1 = g_esrc[k + 1];
        const int s2 = g_esrc[k + 2], s3 = g_esrc[k + 3];
        const int s4 = g_esrc[k + 4], s5 = g_esrc[k + 5];
        const int s6 = g_esrc[k + 6], s7 = g_esrc[k + 7];
        const float v0 = tr_in[s0 * DH + lane], v1 = tr_in[s1 * DH + lane];
        const float v2 = tr_in[s2 * DH + lane], v3 = tr_in[s3 * DH + lane];
        const float v4 = tr_in[s4 * DH + lane], v5 = tr_in[s5 * DH + lane];
        const float v6 = tr_in[s6 * DH + lane], v7 = tr_in[s7 * DH + lane];
        acc += ((v0 + v1) + (v2 + v3)) + ((v4 + v5) + (v6 + v7));
    }
    for (; k < end; k++) acc += tr_in[g_esrc[k] * DH + lane];

    const float h = elu1(acc + root_in[node * DH + lane]);
    ull hd;
    DUP_X2(hd, h);                                // ONE dup per thread
    hs2[w][lane] = hd;
    __syncwarp();

    ull a2 = 0ULL;
#pragma unroll
    for (int kk = 0; kk < 32; kk++)
        FMA_X2(a2, hs2[w][kk], Wp[kk * 32 + lane]);   // LDS.64 bcast + FMA2

    float m, r;
    UNPK_X2(m, r, a2);
    tr_out[node * DH + lane]   = m;
    root_out[node * DH + lane] = r + bs[lane];
}

// ---------------------------------------------------------------------------
// Fused layer 3 + pool: reads a-buffers; h = elu(aggr + root); atomic pool.
// Gather MLP=8.
// ---------------------------------------------------------------------------
__global__ __launch_bounds__(256) void k_flayer3_pool(const void* __restrict__ b_raw)
{
    const int tid  = threadIdx.x;
    const int w    = tid >> 5;
    const int lane = tid & 31;
    const int node = (blockIdx.x << 3) + w;
    if (node >= NN) return;

    const int beg = g_off[node];
    const int end = beg + g_cnt[node];
    float acc = 0.f;
    int k = beg;
    for (; k + 7 < end; k += 8) {
        const int s0 = g_esrc[k + 0], s1 = g_esrc[k + 1];
        const int s2 = g_esrc[k + 2], s3 = g_esrc[k + 3];
        const int s4 = g_esrc[k + 4], s5 = g_esrc[k + 5];
        const int s6 = g_esrc[k + 6], s7 = g_esrc[k + 7];
        const float v0 = g_tr_a[s0 * DH + lane], v1 = g_tr_a[s1 * DH + lane];
        const float v2 = g_tr_a[s2 * DH + lane], v3 = g_tr_a[s3 * DH + lane];
        const float v4 = g_tr_a[s4 * DH + lane], v5 = g_tr_a[s5 * DH + lane];
        const float v6 = g_tr_a[s6 * DH + lane], v7 = g_tr_a[s7 * DH + lane];
        acc += ((v0 + v1) + (v2 + v3)) + ((v4 + v5) + (v6 + v7));
    }
    for (; k < end; k++) acc += g_tr_a[g_esrc[k] * DH + lane];

    const float h = elu1(acc + g_root_a[node * DH + lane]);
    const int g = batch_at(b_raw, node, g_flag_b);
    atomicAdd(&g_sums[g * DH + lane], h);
}

// ---------------------------------------------------------------------------
// Head: pooled mean -> linear[32,2] -> log_softmax
// ---------------------------------------------------------------------------
__global__ void k_head(const float* __restrict__ Wlin, const float* __restrict__ blin,
                       float* __restrict__ out)
{
    const int gph = threadIdx.x;
    if (gph >= NG) return;
    const int cnt = g_gstart[gph + 1] - g_gstart[gph];
    const float inv = 1.f / fmaxf((float)cnt, 1.f);
    float l0 = blin[0], l1 = blin[1];
#pragma unroll
    for (int c = 0; c < DH; c++) {
        const float p = g_sums[gph * DH + c] * inv;
        l0 += p * Wlin[c * 2 + 0];
        l1 += p * Wlin[c * 2 + 1];
    }
    const float m   = fmaxf(l0, l1);
    const float lse = m + logf(expf(l0 - m) + expf(l1 - m));
    out[gph * 2 + 0] = l0 - lse;
    out[gph * 2 + 1] = l1 - lse;
}

// ---------------------------------------------------------------------------
extern "C" void kernel_launch(void* const* d_in, const int* in_sizes, int n_in,
                              void* d_out, int out_size)
{
    const void *p_x = 0, *p_ei = 0, *p_batch = 0;
    const void *p_W1[2] = {0, 0};
    const void *p_W23[4] = {0, 0, 0, 0};
    const void *p_b[3] = {0, 0, 0};
    const void *p_Wlin = 0, *p_blin = 0;
    int n64 = 0, n1024 = 0, n32 = 0;
    for (int i = 0; i < n_in; i++) {
        const int s = in_sizes[i];
        if      (s == NN * DIN) p_x = d_in[i];
        else if (s == 2 * NE)   p_ei = d_in[i];
        else if (s == NN)       p_batch = d_in[i];
        else if (s == DIN * DH) { if (n64 < 2) p_W1[n64++] = d_in[i]; }
        else if (s == DH * DH)  { if (n1024 < 4) p_W23[n1024++] = d_in[i]; }
        else if (s == DH)       { if (n32 < 3) p_b[n32++] = d_in[i]; }
        else if (s == DH * 2)   p_Wlin = d_in[i];
        else if (s == 2)        p_blin = d_in[i];
    }
    const float* x    = (const float*)p_x;
    const float* W1r  = (const float*)p_W1[0];
    const float* W1l  = (const float*)p_W1[1];
    const float* b1   = (const float*)p_b[0];
    const float* W2r  = (const float*)p_W23[0];
    const float* W2l  = (const float*)p_W23[1];
    const float* b2   = (const float*)p_b[1];
    const float* W3r  = (const float*)p_W23[2];
    const float* W3l  = (const float*)p_W23[3];
    const float* b3   = (const float*)p_b[2];
    const float* Wlin = (const float*)p_Wlin;
    const float* blin = (const float*)p_blin;
    float* out = (float*)d_out;

    const int FBLKS = (NN + 7) / 8;               // 6250 (warp per node)

    k_detect_zero<<<NBLK, 256>>>((const unsigned*)p_ei, (const unsigned*)p_batch);
    k_hist<<<EBLK2, 256>>>(p_ei);
    k_scan_bounds<<<NBLK, 256>>>(p_batch);
    k_gemm1_scatter<<<GBLK + SCB, 256>>>(x, W1r, W1l, b1, p_ei);
    k_flayer<<<FBLKS, 256>>>(0, W2r, W2l, b2);    // a -> b (L1 act + L2 linear)
    k_flayer<<<FBLKS, 256>>>(1, W3r, W3l, b3);    // b -> a (L2 act + L3 linear)
    k_flayer3_pool<<<FBLKS, 256>>>(p_batch);      // L3 act + pool
    k_head<<<1, 64>>>(Wlin, blin, out);
}

// round 17
// speedup vs baseline: 1.0974x; 1.0974x over previous
#include <cuda_runtime.h>
#include <math.h>

#define NN 50000
#define NE 400000
#define NG 64
#define DIN 200
#define DH 32
#define NBLK 196    // ceil(NN/256)
#define EBLK2 782   // ceil(NE/512)  (hist: 256 thr x 2 edges)
#define GBLK 391    // ceil(NN/128)  (GEMM blocks: 256 thr, 128 nodes, 64 cols)
#define SCB 782     // ceil(NE/512)  (scatter blocks: 256 thr x 2 edges)

// ---------------- scratch (device globals — no allocation allowed) ----------
// NOTE: never pass these as kernel args from host code (host shadow symbol +
// ATS silently reads zeros). Select ping-pong buffers with an int in device
// code. ALL scratch explicitly zeroed at the top of every launch — replays
// identical by construction. NO __threadfence (per-block CCTL.IVALL = L1D
// flush; measured disaster). NEVER widen smem operand storage to pre-pack
// f32x2 (rounds 13 & 16: doubling crossbar bytes regressed both times; the
// DUPs were already off the critical path). Keep smem bytes/FMA2 <= ~10.
__device__ __align__(16) float g_tr_a[NN * DH];
__device__ __align__(16) float g_tr_b[NN * DH];
__device__ __align__(16) float g_root_a[NN * DH];
__device__ __align__(16) float g_root_b[NN * DH];
__device__ float g_sums[NG * DH];

__device__ int g_flag_ei;    // nonzero -> edge_index is int32
__device__ int g_flag_b;     // nonzero -> batch is int32

__device__ int g_cnt[NN];
__device__ int g_off[NN];
__device__ int g_cur[NN];
__device__ int g_total;
__device__ int g_esrc[NE];   // stores src*DH (pre-scaled: gathers use +lane)
__device__ int g_gstart[NG + 1];

__device__ __forceinline__ float elu1(float v) { return v > 0.f ? v : expm1f(v); }

#define FMA_X2(acc, a, b) \
    asm("fma.rn.f32x2 %0, %1, %2, %0;" : "+l"(acc) : "l"(a), "l"(b))
#define DUP_X2(out, x) \
    asm("mov.b64 %0, {%1, %1};" : "=l"(out) : "r"(__float_as_uint(x)))
#define UNPK_X2(lo, hi, in) \
    asm("mov.b64 {%0, %1}, %2;" : "=f"(lo), "=f"(hi) : "l"(in))
#define PACK_X2(out, lo, hi) \
    asm("mov.b64 %0, {%1, %2};" : "=l"(out) : "f"(lo), "f"(hi))

// ---------------------------------------------------------------------------
// dtype decode helpers (clamped)
// ---------------------------------------------------------------------------
__device__ __forceinline__ int edge_at(const void* ei_raw, int idx, int is32)
{
    int v = is32 ? ((const int*)ei_raw)[idx] : (int)((const long long*)ei_raw)[idx];
    v &= 0x7fffffff;
    return (v < NN) ? v : 0;
}

__device__ __forceinline__ int batch_at(const void* b_raw, int i, int is32)
{
    int g = is32 ? ((const int*)b_raw)[i] : (int)((const long long*)b_raw)[i];
    g &= 0x7fffffff;
    return (g < NG) ? g : (NG - 1);
}

// ---------------------------------------------------------------------------
// Kernel 1: zero scratch + dtype detection (block 0 samples odd 32-bit words:
// int64 values < 2^31 have zero high words; int32 payloads essentially never do)
// ---------------------------------------------------------------------------
__global__ void k_detect_zero(const unsigned* __restrict__ ei_w,
                              const unsigned* __restrict__ b_w)
{
    const int i = blockIdx.x * blockDim.x + threadIdx.x;
    if (i < NN) g_cnt[i] = 0;
    if (i < NG * DH) g_sums[i] = 0.f;
    if (i == 0) g_total = 0;

    if (blockIdx.x == 0) {
        __shared__ int s_ei, s_b;
        const int tid = threadIdx.x;
        if (tid == 0) { s_ei = 0; s_b = 0; }
        __syncthreads();
        { const int k = tid * 1562;  if (ei_w[2 * k + 1] != 0) atomicOr(&s_ei, 1); }
        { const int k = 24744 + tid; if (b_w[2 * k + 1] != 0)  atomicOr(&s_b, 1); }
        __syncthreads();
        if (tid == 0) { g_flag_ei = s_ei; g_flag_b = s_b; }
    }
}

// ---------------------------------------------------------------------------
// Kernel 2: dst histogram (decodes only dst half of raw edge_index)
// ---------------------------------------------------------------------------
__global__ void k_hist(const void* __restrict__ ei_raw)
{
    const int tid = blockIdx.x * 256 + threadIdx.x;
    const int is32 = g_flag_ei;
#pragma unroll
    for (int q = 0; q < 2; q++) {
        const int e = tid + q * (EBLK2 * 256);
        if (e < NE) atomicAdd(&g_cnt[edge_at(ei_raw, NE + e, is32)], 1);
    }
}

// ---------------------------------------------------------------------------
// Kernel 3: single-pass scan (block scan + atomic base; bases need not be
// monotone since consumers use beg + cnt) fused with graph-boundary build.
// ---------------------------------------------------------------------------
__global__ void k_scan_bounds(const void* __restrict__ b_raw)
{
    __shared__ int s[256];
    __shared__ int base_sh;
    const int tid = threadIdx.x;
    const int i = blockIdx.x * 256 + tid;
    const int v = (i < NN) ? g_cnt[i] : 0;
    s[tid] = v;
    __syncthreads();
#pragma unroll
    for (int d = 1; d < 256; d <<= 1) {
        const int t = (tid >= d) ? s[tid - d] : 0;
        __syncthreads();
        s[tid] += t;
        __syncthreads();
    }
    if (tid == 255) base_sh = atomicAdd(&g_total, s[255]);
    __syncthreads();
    if (i < NN) {
        const int o = base_sh + s[tid] - v;
        g_off[i] = o;
        g_cur[i] = o;
    }

    if (i < NN) {
        const int is32 = g_flag_b;
        const int g  = batch_at(b_raw, i, is32);
        const int gp = (i == 0) ? -1 : batch_at(b_raw, i - 1, is32);
        for (int q = gp + 1; q <= g; q++) g_gstart[q] = i;
        if (i == NN - 1)
            for (int q = g + 1; q <= NG; q++) g_gstart[q] = NN;
    }
}

// ---------------------------------------------------------------------------
// Kernel 4 (fused): blocks [0,GBLK) = GEMM1; blocks [GBLK,GBLK+SCB) = CSR
// scatter (decodes raw edges; stores src*DH pre-scaled for gather kernels).
// GEMM1: [50000,200] @ [W1r|W1l][200,64], packed f32x2, double-buffered smem.
// 256 threads / 128 nodes / 64 cols; 8 nodes x 4 cols per thread (5 B smem
// per FMA2 -> crossbar-safe); ~80 regs -> 3 CTAs/SM = 24 warps.
// ---------------------------------------------------------------------------
__global__ __launch_bounds__(256) void k_gemm1_scatter(const float* __restrict__ x,
                                                       const float* __restrict__ Wr,
                                                       const float* __restrict__ Wl,
                                                       const float* __restrict__ b,
                                                       const void* __restrict__ ei_raw)
{
    if (blockIdx.x >= GBLK) {
        const int base = (blockIdx.x - GBLK) * 512 + threadIdx.x;
        const int is32 = g_flag_ei;
#pragma unroll
        for (int q = 0; q < 2; q++) {
            const int e = base + q * 256;
            if (e < NE) {
                const int d = edge_at(ei_raw, NE + e, is32);
                const int s = edge_at(ei_raw, e, is32);
                const int pos = atomicAdd(&g_cur[d], 1);
                g_esrc[pos] = s * DH;               // pre-scaled
            }
        }
        return;
    }

    __shared__ __align__(16) float Xs[2][8 * 128];   // [buf][k][node]
    __shared__ __align__(16) float Wsc[2][8 * 64];   // [buf][k*64+c]
    __shared__ float bs[32];

    const int tid = threadIdx.x;
    const int n0  = blockIdx.x * 128;
    if (tid < 32) bs[tid] = b[tid];

    const int cg = tid & 15;       // col group (4 cols), 0..15
    const int ng = tid >> 4;       // node group (8 nodes), 0..15

    unsigned long long acc2[8][2]; // [node][col pair]
#pragma unroll
    for (int i = 0; i < 8; i++) { acc2[i][0] = 0ULL; acc2[i][1] = 0ULL; }

    const bool is_x = tid < 128;
    const int  nld = n0 + tid;
    const bool vld = is_x && (nld < NN);
    const float4* xrow = reinterpret_cast<const float4*>(x + (long)nld * DIN);

    float4 xa, xb;
    float  wv[2];

#define LOAD_TILE(t)                                                          \
    do {                                                                      \
        if (is_x) {                                                           \
            xa = make_float4(0.f, 0.f, 0.f, 0.f); xb = xa;                    \
            if (vld) { xa = xrow[(t) * 2]; xb = xrow[(t) * 2 + 1]; }          \
        }                                                                     \
        _Pragma("unroll")                                                     \
        for (int j = 0; j < 2; j++) {                                         \
            const int idx = j * 256 + tid;       /* 0..511 = kk*64+c */       \
            const int kk = idx >> 6, c = idx & 63;                            \
            wv[j] = (c < 32) ? Wr[((t) * 8 + kk) * 32 + c]                    \
                             : Wl[((t) * 8 + kk) * 32 + c - 32];              \
        }                                                                     \
    } while (0)

#define STORE_TILE(bf)                                                        \
    do {                                                                      \
        if (is_x) {                                                           \
            Xs[bf][0 * 128 + tid] = xa.x; Xs[bf][1 * 128 + tid] = xa.y;       \
            Xs[bf][2 * 128 + tid] = xa.z; Xs[bf][3 * 128 + tid] = xa.w;       \
            Xs[bf][4 * 128 + tid] = xb.x; Xs[bf][5 * 128 + tid] = xb.y;       \
            Xs[bf][6 * 128 + tid] = xb.z; Xs[bf][7 * 128 + tid] = xb.w;       \
        }                                                                     \
        _Pragma("unroll")                                                     \
        for (int j = 0; j < 2; j++) Wsc[bf][j * 256 + tid] = wv[j];           \
    } while (0)

    LOAD_TILE(0);
    STORE_TILE(0);
    __syncthreads();

    int buf = 0;
    for (int t = 0; t < 25; t++) {
        if (t < 24) LOAD_TILE(t + 1);                // LDG in flight during compute

#pragma unroll
        for (int kk = 0; kk < 8; kk++) {
            const float4* xp = reinterpret_cast<const float4*>(Xs[buf] + kk * 128 + ng * 8);
            const float4 a0 = xp[0], a1 = xp[1];
            const unsigned long long* wp =
                reinterpret_cast<const unsigned long long*>(Wsc[buf] + kk * 64 + cg * 4);
            const unsigned long long w0 = wp[0], w1p = wp[1];
            const float xv[8] = {a0.x, a0.y, a0.z, a0.w, a1.x, a1.y, a1.z, a1.w};
#pragma unroll
            for (int i = 0; i < 8; i++) {
                unsigned long long xd;
                DUP_X2(xd, xv[i]);
                FMA_X2(acc2[i][0], xd, w0);
                FMA_X2(acc2[i][1], xd, w1p);
            }
        }

        if (t < 24) STORE_TILE(buf ^ 1);             // other buffer: race-free
        __syncthreads();
        buf ^= 1;
    }
#undef LOAD_TILE
#undef STORE_TILE

    const int c0 = cg * 4;
#pragma unroll
    for (int i = 0; i < 8; i++) {
        const int node = n0 + ng * 8 + i;
        if (node >= NN) continue;
        float c[4];
        UNPK_X2(c[0], c[1], acc2[i][0]);
        UNPK_X2(c[2], c[3], acc2[i][1]);
        float4 v = make_float4(c[0], c[1], c[2], c[3]);
        if (cg < 8) {
            *reinterpret_cast<float4*>(g_tr_a + node * DH + c0) = v;
        } else {
            const int cc = c0 - 32;
            v.x += bs[cc + 0]; v.y += bs[cc + 1]; v.z += bs[cc + 2]; v.w += bs[cc + 3];
            *reinterpret_cast<float4*>(g_root_a + node * DH + cc) = v;
        }
    }
}

// ---------------------------------------------------------------------------
// Fused layer kernel (layers 1->2, 2->3): warp per node; buffers picked by sel
// in device code (sel=0: a->b, sel=1: b->a). Gather MLP=8, pre-scaled esrc
// (address = esrc[k] + lane, single IADD).
// ---------------------------------------------------------------------------
__global__ __launch_bounds__(256) void k_flayer(int sel,
                                                const float* __restrict__ Wr,
                                                const float* __restrict__ Wl,
                                                const float* __restrict__ b)
{
    __shared__ __align__(16) unsigned long long Wp[32 * 32];  // [k][lane]=(Wr,Wl)
    __shared__ float bs[32];
    __shared__ float hs[8][32];

    const int tid = threadIdx.x;
    for (int i = tid; i < 1024; i += 256) {
        const int k = i >> 5, c = i & 31;
        unsigned long long p;
        PACK_X2(p, Wr[k * 32 + c], Wl[k * 32 + c]);
        Wp[i] = p;
    }
    if (tid < 32) bs[tid] = b[tid];
    __syncthreads();

    const float* tr_in   = sel ? g_tr_b   : g_tr_a;
    const float* root_in = sel ? g_root_b : g_root_a;
    float* tr_out   = sel ? g_tr_a   : g_tr_b;
    float* root_out = sel ? g_root_a : g_root_b;

    const int w    = tid >> 5;
    const int lane = tid & 31;
    const int node = (blockIdx.x << 3) + w;
    if (node >= NN) return;

    const float* trl = tr_in + lane;              // lane-offset base
    const int beg = g_off[node];
    const int end = beg + g_cnt[node];
    float acc = 0.f;
    int k = beg;
    for (; k + 7 < end; k += 8) {                 // MLP=8 over L2-latency gathers
        const int s0 = g_esrc[k + 0], s1 = g_esrc[k + 1];
        const int s2 = g_esrc[k + 2], s3 = g_esrc[k + 3];
        const int s4 = g_esrc[k + 4], s5 = g_esrc[k + 5];
        const int s6 = g_esrc[k + 6], s7 = g_esrc[k + 7];
        const float v0 = trl[s0], v1 = trl[s1];
        const float v2 = trl[s2], v3 = trl[s3];
        const float v4 = trl[s4], v5 = trl[s5];
        const float v6 = trl[s6], v7 = trl[s7];
        acc += ((v0 + v1) + (v2 + v3)) + ((v4 + v5) + (v6 + v7));
    }
    for (; k < end; k++) acc += trl[g_esrc[k]];

    const float h = elu1(acc + root_in[node * DH + lane]);
    hs[w][lane] = h;
    __syncwarp();

    unsigned long long a2 = 0ULL;
#pragma unroll
    for (int kk = 0; kk < 32; kk++) {
        unsigned long long hd;
        DUP_X2(hd, hs[w][kk]);                    // LDS broadcast
        FMA_X2(a2, hd, Wp[kk * 32 + lane]);
    }
    float m, r;
    UNPK_X2(m, r, a2);
    tr_out[node * DH + lane]   = m;
    root_out[node * DH + lane] = r + bs[lane];
}

// ---------------------------------------------------------------------------
// Fused layer 3 + pool: reads a-buffers; h = elu(aggr + root); atomic pool.
// Gather MLP=8, pre-scaled esrc.
// ---------------------------------------------------------------------------
__global__ __launch_bounds__(256) void k_flayer3_pool(const void* __restrict__ b_raw)
{
    const int tid  = threadIdx.x;
    const int w    = tid >> 5;
    const int lane = tid & 31;
    const int node = (blockIdx.x << 3) + w;
    if (node >= NN) return;

    const float* trl = g_tr_a + lane;
    const int beg = g_off[node];
    const int end = beg + g_cnt[node];
    float acc = 0.f;
    int k = beg;
    for (; k + 7 < end; k += 8) {
        const int s0 = g_esrc[k + 0], s1 = g_esrc[k + 1];
        const int s2 = g_esrc[k + 2], s3 = g_esrc[k + 3];
        const int s4 = g_esrc[k + 4], s5 = g_esrc[k + 5];
        const int s6 = g_esrc[k + 6], s7 = g_esrc[k + 7];
        const float v0 = trl[s0], v1 = trl[s1];
        const float v2 = trl[s2], v3 = trl[s3];
        const float v4 = trl[s4], v5 = trl[s5];
        const float v6 = trl[s6], v7 = trl[s7];
        acc += ((v0 + v1) + (v2 + v3)) + ((v4 + v5) + (v6 + v7));
    }
    for (; k < end; k++) acc += trl[g_esrc[k]];

    const float h = elu1(acc + g_root_a[node * DH + lane]);
    const int g = batch_at(b_raw, node, g_flag_b);
    atomicAdd(&g_sums[g * DH + lane], h);
}

// ---------------------------------------------------------------------------
// Head: pooled mean -> linear[32,2] -> log_softmax
// ---------------------------------------------------------------------------
__global__ void k_head(const float* __restrict__ Wlin, const float* __restrict__ blin,
                       float* __restrict__ out)
{
    const int gph = threadIdx.x;
    if (gph >= NG) return;
    const int cnt = g_gstart[gph + 1] - g_gstart[gph];
    const float inv = 1.f / fmaxf((float)cnt, 1.f);
    float l0 = blin[0], l1 = blin[1];
#pragma unroll
    for (int c = 0; c < DH; c++) {
        const float p = g_sums[gph * DH + c] * inv;
        l0 += p * Wlin[c * 2 + 0];
        l1 += p * Wlin[c * 2 + 1];
    }
    const float m   = fmaxf(l0, l1);
    const float lse = m + logf(expf(l0 - m) + expf(l1 - m));
    out[gph * 2 + 0] = l0 - lse;
    out[gph * 2 + 1] = l1 - lse;
}

// ---------------------------------------------------------------------------
extern "C" void kernel_launch(void* const* d_in, const int* in_sizes, int n_in,
                              void* d_out, int out_size)
{
    const void *p_x = 0, *p_ei = 0, *p_batch = 0;
    const void *p_W1[2] = {0, 0};
    const void *p_W23[4] = {0, 0, 0, 0};
    const void *p_b[3] = {0, 0, 0};
    const void *p_Wlin = 0, *p_blin = 0;
    int n64 = 0, n1024 = 0, n32 = 0;
    for (int i = 0; i < n_in; i++) {
        const int s = in_sizes[i];
        if      (s == NN * DIN) p_x = d_in[i];
        else if (s == 2 * NE)   p_ei = d_in[i];
        else if (s == NN)       p_batch = d_in[i];
        else if (s == DIN * DH) { if (n64 < 2) p_W1[n64++] = d_in[i]; }
        else if (s == DH * DH)  { if (n1024 < 4) p_W23[n1024++] = d_in[i]; }
        else if (s == DH)       { if (n32 < 3) p_b[n32++] = d_in[i]; }
        else if (s == DH * 2)   p_Wlin = d_in[i];
        else if (s == 2)        p_blin = d_in[i];
    }
    const float* x    = (const float*)p_x;
    const float* W1r  = (const float*)p_W1[0];
    const float* W1l  = (const float*)p_W1[1];
    const float* b1   = (const float*)p_b[0];
    const float* W2r  = (const float*)p_W23[0];
    const float* W2l  = (const float*)p_W23[1];
    const float* b2   = (const float*)p_b[1];
    const float* W3r  = (const float*)p_W23[2];
    const float* W3l  = (const float*)p_W23[3];
    const float* b3   = (const float*)p_b[2];
    const float* Wlin = (const float*)p_Wlin;
    const float* blin = (const float*)p_blin;
    float* out = (float*)d_out;

    const int FBLKS = (NN + 7) / 8;               // 6250 (warp per node)

    k_detect_zero<<<NBLK, 256>>>((const unsigned*)p_ei, (const unsigned*)p_batch);
    k_hist<<<EBLK2, 256>>>(p_ei);
    k_scan_bounds<<<NBLK, 256>>>(p_batch);
    k_gemm1_scatter<<<GBLK + SCB, 256>>>(x, W1r, W1l, b1, p_ei);
    k_flayer<<<FBLKS, 256>>>(0, W2r, W2l, b2);    // a -> b (L1 act + L2 linear)
    k_flayer<<<FBLKS, 256>>>(1, W3r, W3l, b3);    // b -> a (L2 act + L3 linear)
    k_flayer3_pool<<<FBLKS, 256>>>(p_batch);      // L3 act + pool
    k_head<<<1, 64>>>(Wlin, blin, out);
}